// round 2
// baseline (speedup 1.0000x reference)
#include <cuda_runtime.h>

// Shapes are fixed by the problem: preds/targets [32, 2048, 512] f32, lengths [32] i32.
#define BB 32
#define TT 2048
#define DD 512
#define TILES 16   // t-tiles per batch row in kernel 1
#define SLOTS (TILES * 2)   // 2 sub-rows per block

// Scratch (device globals: allocation-free, replay-safe because every slot is
// rewritten on every launch).
__device__ float g_S[BB * SLOTS * DD];   // partial diff-sums, 2 MiB
__device__ float g_wordP[BB * TILES];    // per-block word-loss partials (512)
__device__ float g_sentB[BB];            // per-b sentence term (mean over D)

__device__ __forceinline__ float sl1(float d) {
    float ad = fabsf(d);
    return ad < 1.0f ? 0.5f * d * d : ad - 0.5f;
}

// Kernel 1: stream valid rows once; accumulate per-(b,d) diff sums and the
// word-loss partial. grid = (TILES, BB), block = 256 (2 t-rows x 128 d-lanes).
__global__ __launch_bounds__(256)
void k_main(const float* __restrict__ preds,
            const float* __restrict__ targs,
            const int* __restrict__ lens) {
    const int b    = blockIdx.y;
    const int tile = blockIdx.x;
    const int tid  = threadIdx.x;
    const int sub  = tid >> 7;            // 0 or 1: which t-row of the pair
    const int dg   = (tid & 127) << 2;    // float4 column group, covers D=512

    const int len   = lens[b];
    const int chunk = (len + TILES - 1) / TILES;
    const int t0    = tile * chunk;
    const int t1    = min(t0 + chunk, len);

    float4 sd = make_float4(0.f, 0.f, 0.f, 0.f);
    float  w  = 0.f;

    const size_t base = (size_t)b * TT * DD + dg;

    #pragma unroll 4
    for (int t = t0 + sub; t < t1; t += 2) {
        const size_t off = base + (size_t)t * DD;
        const float4 pv = *reinterpret_cast<const float4*>(preds + off);
        const float4 tv = *reinterpret_cast<const float4*>(targs + off);
        float dx = pv.x - tv.x;
        float dy = pv.y - tv.y;
        float dz = pv.z - tv.z;
        float dw = pv.w - tv.w;
        sd.x += dx; sd.y += dy; sd.z += dz; sd.w += dw;
        w += sl1(dx) + sl1(dy) + sl1(dz) + sl1(dw);
    }

    // Write partial diff-sums (plain stores; unique slot per (block, sub, dg)).
    const size_t si = (((size_t)b * SLOTS) + tile * 2 + sub) * DD + dg;
    *reinterpret_cast<float4*>(g_S + si) = sd;

    // Block-reduce the word partial.
    __shared__ float sw[256];
    sw[tid] = w;
    __syncthreads();
    #pragma unroll
    for (int s = 128; s > 0; s >>= 1) {
        if (tid < s) sw[tid] += sw[tid + s];
        __syncthreads();
    }
    if (tid == 0) g_wordP[b * TILES + tile] = sw[0];
}

// Kernel 2: fold the 32 partials per (b,d), apply smooth_l1(S/len), mean over D.
// grid = BB, block = 128 (one float4 group per thread).
__global__ __launch_bounds__(128)
void k_sent(const int* __restrict__ lens) {
    const int b   = blockIdx.x;
    const int tid = threadIdx.x;
    const int dg  = tid << 2;

    float4 s = make_float4(0.f, 0.f, 0.f, 0.f);
    #pragma unroll
    for (int j = 0; j < SLOTS; j++) {
        const float4 v = *reinterpret_cast<const float4*>(
            g_S + (((size_t)b * SLOTS) + j) * DD + dg);
        s.x += v.x; s.y += v.y; s.z += v.z; s.w += v.w;
    }
    const float invlen = 1.0f / (float)lens[b];
    float w = sl1(s.x * invlen) + sl1(s.y * invlen)
            + sl1(s.z * invlen) + sl1(s.w * invlen);

    __shared__ float sw[128];
    sw[tid] = w;
    __syncthreads();
    #pragma unroll
    for (int s2 = 64; s2 > 0; s2 >>= 1) {
        if (tid < s2) sw[tid] += sw[tid + s2];
        __syncthreads();
    }
    if (tid == 0) g_sentB[b] = sw[0] * (1.0f / (float)DD);
}

// Kernel 3: final combine. 1 block, 512 threads.
__global__ __launch_bounds__(512)
void k_final(const int* __restrict__ lens, float* __restrict__ out) {
    const int tid = threadIdx.x;
    __shared__ float swd[512];
    __shared__ float ssn[512];
    __shared__ int   sln[512];

    swd[tid] = g_wordP[tid];
    ssn[tid] = (tid < BB) ? g_sentB[tid] : 0.f;
    sln[tid] = (tid < BB) ? lens[tid] : 0;
    __syncthreads();
    #pragma unroll
    for (int s = 256; s > 0; s >>= 1) {
        if (tid < s) {
            swd[tid] += swd[tid + s];
            ssn[tid] += ssn[tid + s];
            sln[tid] += sln[tid + s];
        }
        __syncthreads();
    }
    if (tid == 0) {
        const float n_valid = (float)sln[0] * (float)DD;  // <= 2^25, exact
        out[0] = swd[0] / n_valid + ssn[0] * (1.0f / (float)BB);
    }
}

extern "C" void kernel_launch(void* const* d_in, const int* in_sizes, int n_in,
                              void* d_out, int out_size) {
    const float* preds = (const float*)d_in[0];
    const float* targs = (const float*)d_in[1];
    const int*   lens  = (const int*)d_in[2];
    float* out = (float*)d_out;

    k_main<<<dim3(TILES, BB), 256>>>(preds, targs, lens);
    k_sent<<<BB, 128>>>(lens);
    k_final<<<1, 512>>>(lens, out);
}

// round 3
// speedup vs baseline: 1.2076x; 1.2076x over previous
#include <cuda_runtime.h>

// Fixed shapes: preds/targets [32, 2048, 512] f32, lengths [32] i32.
#define BB 32
#define TT 2048
#define DD 512
#define TILES 64   // t-tiles per batch row (strided assignment)

// Scratch (device globals; every slot rewritten each launch -> replay-safe).
__device__ float    g_S[BB * TILES * DD];   // per-(b,tile,d) diff-sum partials, 4 MiB
__device__ float    g_wordP[BB * TILES];    // per-block word-loss partials (2048)
__device__ float    g_sentB[BB];            // per-b sentence term
__device__ unsigned g_ctr;                  // wrap-around arrival counter (self-resetting)

__device__ __forceinline__ float sl1(float d) {
    float ad = fabsf(d);
    return ad < 1.0f ? 0.5f * d * d : ad - 0.5f;
}

// Kernel 1: stream valid rows once. grid = (TILES, BB), block = 256
// (2 t-rows in flight x 128 float4 lanes). Strided t => balanced blocks.
__global__ __launch_bounds__(256)
void k_main(const float* __restrict__ preds,
            const float* __restrict__ targs,
            const int* __restrict__ lens) {
    const int b    = blockIdx.y;
    const int tile = blockIdx.x;
    const int tid  = threadIdx.x;
    const int sub  = tid >> 7;            // 0/1: which row of the pair
    const int lane = tid & 127;
    const int dg   = lane << 2;           // float4 column group (covers D=512)

    const int len = lens[b];

    float4 sd = make_float4(0.f, 0.f, 0.f, 0.f);
    float  w  = 0.f;

    const size_t base = (size_t)b * TT * DD + dg;

    #pragma unroll 4
    for (int t = tile + sub * TILES; t < len; t += 2 * TILES) {
        const size_t off = base + (size_t)t * DD;
        const float4 pv = *reinterpret_cast<const float4*>(preds + off);
        const float4 tv = *reinterpret_cast<const float4*>(targs + off);
        float dx = pv.x - tv.x;
        float dy = pv.y - tv.y;
        float dz = pv.z - tv.z;
        float dw = pv.w - tv.w;
        sd.x += dx; sd.y += dy; sd.z += dz; sd.w += dw;
        w += sl1(dx) + sl1(dy) + sl1(dz) + sl1(dw);
    }

    // Combine sub0+sub1 diff-sums via shared, store one slot per (b,tile).
    __shared__ float4 sh4[128];
    __shared__ float  sw[256];
    if (sub == 1) sh4[lane] = sd;
    sw[tid] = w;
    __syncthreads();
    if (sub == 0) {
        const float4 o = sh4[lane];
        sd.x += o.x; sd.y += o.y; sd.z += o.z; sd.w += o.w;
        *reinterpret_cast<float4*>(g_S + ((size_t)(b * TILES + tile)) * DD + dg) = sd;
    }

    // Block-reduce the word partial.
    #pragma unroll
    for (int s = 128; s > 0; s >>= 1) {
        if (tid < s) sw[tid] += sw[tid + s];
        __syncthreads();
    }
    if (tid == 0) g_wordP[b * TILES + tile] = sw[0];
}

// Kernel 2: fold TILES partials per (b,d), smooth_l1(S/len), mean over D;
// the LAST block to finish also does the final scalar combine.
// grid = BB, block = 128.
__global__ __launch_bounds__(128)
void k_sent(const int* __restrict__ lens, float* __restrict__ out) {
    const int b   = blockIdx.x;
    const int tid = threadIdx.x;
    const int dg  = tid << 2;

    float4 s = make_float4(0.f, 0.f, 0.f, 0.f);
    #pragma unroll
    for (int j = 0; j < TILES; j++) {
        const float4 v = *reinterpret_cast<const float4*>(
            g_S + ((size_t)(b * TILES + j)) * DD + dg);
        s.x += v.x; s.y += v.y; s.z += v.z; s.w += v.w;
    }
    const float invlen = 1.0f / (float)lens[b];
    float w = sl1(s.x * invlen) + sl1(s.y * invlen)
            + sl1(s.z * invlen) + sl1(s.w * invlen);

    __shared__ float sw[128];
    __shared__ bool  is_last;
    sw[tid] = w;
    __syncthreads();
    #pragma unroll
    for (int s2 = 64; s2 > 0; s2 >>= 1) {
        if (tid < s2) sw[tid] += sw[tid + s2];
        __syncthreads();
    }
    if (tid == 0) {
        g_sentB[b] = sw[0] * (1.0f / (float)DD);
        __threadfence();
        // atomicInc with limit BB-1 wraps to 0 after the BB-th arrival:
        // self-resetting across graph replays.
        unsigned prev = atomicInc(&g_ctr, BB - 1u);
        is_last = (prev == BB - 1u);
    }
    __syncthreads();

    if (is_last) {
        __threadfence();  // acquire: see all blocks' g_sentB/g_wordP writes
        float wsum = 0.f;
        #pragma unroll
        for (int i = tid; i < BB * TILES; i += 128) wsum += g_wordP[i];
        float ssum = 0.f;
        int   lsum = 0;
        if (tid < BB) { ssum = g_sentB[tid]; lsum = lens[tid]; }

        __shared__ float swd[128];
        __shared__ float ssn[128];
        __shared__ int   sln[128];
        swd[tid] = wsum; ssn[tid] = ssum; sln[tid] = lsum;
        __syncthreads();
        #pragma unroll
        for (int s2 = 64; s2 > 0; s2 >>= 1) {
            if (tid < s2) {
                swd[tid] += swd[tid + s2];
                ssn[tid] += ssn[tid + s2];
                sln[tid] += sln[tid + s2];
            }
            __syncthreads();
        }
        if (tid == 0) {
            const float n_valid = (float)sln[0] * (float)DD;  // <= 2^25, exact
            out[0] = swd[0] / n_valid + ssn[0] * (1.0f / (float)BB);
        }
    }
}

extern "C" void kernel_launch(void* const* d_in, const int* in_sizes, int n_in,
                              void* d_out, int out_size) {
    const float* preds = (const float*)d_in[0];
    const float* targs = (const float*)d_in[1];
    const int*   lens  = (const int*)d_in[2];
    float* out = (float*)d_out;

    k_main<<<dim3(TILES, BB), 256>>>(preds, targs, lens);
    k_sent<<<BB, 128>>>(lens, out);
}

// round 4
// speedup vs baseline: 1.2604x; 1.0437x over previous
#include <cuda_runtime.h>

// Fixed shapes: preds/targets [32, 2048, 512] f32, lengths [32] i32.
#define BB 32
#define TT 2048
#define DD 512
#define TILES 64   // blocks (t-tiles) per batch row, strided t assignment

// Scratch (device globals; every slot rewritten each launch; counters wrap
// back to 0 -> replay-safe, no init kernel needed).
__device__ float    g_S[BB * TILES * DD];   // per-(b,tile,d) diff-sum partials, 4 MiB
__device__ float    g_wordP[BB * TILES];    // per-block word-loss partials (2048)
__device__ float    g_sentB[BB];            // per-b sentence term
__device__ unsigned g_ctrB[BB];             // per-b arrival counters (wrap at TILES-1)
__device__ unsigned g_ctr;                  // global arrival counter (wrap at BB-1)

__device__ __forceinline__ float sl1(float d) {
    float ad = fabsf(d);
    return ad < 1.0f ? 0.5f * d * d : ad - 0.5f;
}

// One fused kernel. grid = (TILES, BB), block = 256 (2 t-rows x 128 float4 lanes).
__global__ __launch_bounds__(256)
void k_fused(const float* __restrict__ preds,
             const float* __restrict__ targs,
             const int* __restrict__ lens,
             float* __restrict__ out) {
    const int b    = blockIdx.y;
    const int tile = blockIdx.x;
    const int tid  = threadIdx.x;
    const int sub  = tid >> 7;            // 0/1
    const int lane = tid & 127;
    const int dg   = lane << 2;           // float4 column group (covers D=512)

    const int len = lens[b];

    // ---- Phase 1: stream valid rows once (HBM-bound) ----
    float4 sd = make_float4(0.f, 0.f, 0.f, 0.f);
    float  w  = 0.f;

    const size_t base = (size_t)b * TT * DD + dg;

    #pragma unroll 4
    for (int t = tile + sub * TILES; t < len; t += 2 * TILES) {
        const size_t off = base + (size_t)t * DD;
        const float4 pv = *reinterpret_cast<const float4*>(preds + off);
        const float4 tv = *reinterpret_cast<const float4*>(targs + off);
        float dx = pv.x - tv.x;
        float dy = pv.y - tv.y;
        float dz = pv.z - tv.z;
        float dw = pv.w - tv.w;
        sd.x += dx; sd.y += dy; sd.z += dz; sd.w += dw;
        w += sl1(dx) + sl1(dy) + sl1(dz) + sl1(dw);
    }

    // Combine sub0+sub1 diff-sums via shared; store one slot per (b,tile).
    __shared__ float4 sh4[128];
    __shared__ float  sw[256];
    __shared__ bool   is_last_b, is_last_g;
    if (sub == 1) sh4[lane] = sd;
    sw[tid] = w;
    __syncthreads();
    if (sub == 0) {
        const float4 o = sh4[lane];
        sd.x += o.x; sd.y += o.y; sd.z += o.z; sd.w += o.w;
        *reinterpret_cast<float4*>(g_S + ((size_t)(b * TILES + tile)) * DD + dg) = sd;
    }

    // Block-reduce the word partial.
    #pragma unroll
    for (int s = 128; s > 0; s >>= 1) {
        if (tid < s) sw[tid] += sw[tid + s];
        __syncthreads();
    }
    if (tid == 0) {
        g_wordP[b * TILES + tile] = sw[0];
        __threadfence();
        // wraps to 0 after TILES arrivals -> self-resetting across replays
        unsigned prev = atomicInc(&g_ctrB[b], TILES - 1u);
        is_last_b = (prev == TILES - 1u);
    }
    __syncthreads();
    if (!is_last_b) return;

    // ---- Phase 2 (last block of this b): reduce 64 partial slots, L2-hot ----
    __threadfence();  // acquire: see all 64 blocks' g_S writes for this b

    float4 s4 = make_float4(0.f, 0.f, 0.f, 0.f);
    const float* Sb = g_S + (size_t)b * TILES * DD;
    #pragma unroll
    for (int j = sub * (TILES / 2); j < (sub + 1) * (TILES / 2); j++) {
        const float4 v = *reinterpret_cast<const float4*>(Sb + (size_t)j * DD + dg);
        s4.x += v.x; s4.y += v.y; s4.z += v.z; s4.w += v.w;
    }
    __syncthreads();   // sh4 reuse
    if (sub == 1) sh4[lane] = s4;
    __syncthreads();
    float wsent = 0.f;
    if (sub == 0) {
        const float4 o = sh4[lane];
        s4.x += o.x; s4.y += o.y; s4.z += o.z; s4.w += o.w;
        const float invlen = 1.0f / (float)len;
        wsent = sl1(s4.x * invlen) + sl1(s4.y * invlen)
              + sl1(s4.z * invlen) + sl1(s4.w * invlen);
    }
    sw[tid] = wsent;
    __syncthreads();
    #pragma unroll
    for (int s = 128; s > 0; s >>= 1) {
        if (tid < s) sw[tid] += sw[tid + s];
        __syncthreads();
    }
    if (tid == 0) {
        g_sentB[b] = sw[0] * (1.0f / (float)DD);
        __threadfence();
        unsigned prev = atomicInc(&g_ctr, BB - 1u);
        is_last_g = (prev == BB - 1u);
    }
    __syncthreads();
    if (!is_last_g) return;

    // ---- Phase 3 (single final block): scalar combine, L2-hot ----
    __threadfence();

    float wsum = 0.f;
    #pragma unroll
    for (int i = tid; i < BB * TILES; i += 256) wsum += g_wordP[i];
    float ssum = 0.f;
    int   lsum = 0;
    if (tid < BB) { ssum = g_sentB[tid]; lsum = lens[tid]; }

    __shared__ float swd[256];
    __shared__ float ssn[256];
    __shared__ int   sln[256];
    swd[tid] = wsum; ssn[tid] = ssum; sln[tid] = lsum;
    __syncthreads();
    #pragma unroll
    for (int s = 128; s > 0; s >>= 1) {
        if (tid < s) {
            swd[tid] += swd[tid + s];
            ssn[tid] += ssn[tid + s];
            sln[tid] += sln[tid + s];
        }
        __syncthreads();
    }
    if (tid == 0) {
        const float n_valid = (float)sln[0] * (float)DD;  // <= 2^25, exact
        out[0] = swd[0] / n_valid + ssn[0] * (1.0f / (float)BB);
    }
}

extern "C" void kernel_launch(void* const* d_in, const int* in_sizes, int n_in,
                              void* d_out, int out_size) {
    const float* preds = (const float*)d_in[0];
    const float* targs = (const float*)d_in[1];
    const int*   lens  = (const int*)d_in[2];
    float* out = (float*)d_out;

    k_fused<<<dim3(TILES, BB), 256>>>(preds, targs, lens, out);
}